// round 1
// baseline (speedup 1.0000x reference)
#include <cuda_runtime.h>
#include <cuda_bf16.h>

// SpatialAttentionLayer_23381801959766
//
// Reference math:
//   attn = softmax(fourier_maps(sensor_locs) @ W, axis=-1)   # rows sum to 1
//   out  = einsum('si,sjk->sjk', attn, X)                    # i summed out
//        = X * (row-sum of softmax) = X  (to fp32 ULP)
//
// The whole layer is algebraically the identity on X. The only achievable
// optimization target is the HBM copy roofline: 2 x 142.6 MB of traffic.

extern "C" void kernel_launch(void* const* d_in, const int* in_sizes, int n_in,
                              void* d_out, int out_size) {
    // Inputs per metadata order: X [S,B,T] fp32, sensor_locs [S,2] fp32,
    // fourier_weights [J,H,H,2] fp32. Output: [S,B,T] fp32 == X.
    const float* X = (const float*)d_in[0];
    cudaMemcpyAsync(d_out, X, (size_t)out_size * sizeof(float),
                    cudaMemcpyDeviceToDevice, 0);
}

// round 2
// speedup vs baseline: 1.0449x; 1.0449x over previous
#include <cuda_runtime.h>
#include <cuda_bf16.h>
#include <cstdint>

// SpatialAttentionLayer_23381801959766
//
// Reference math:
//   attn = softmax(fourier_maps(sensor_locs) @ W, axis=-1)   # rows sum to 1
//   out  = einsum('si,sjk->sjk', attn, X)                    # i summed out
//        = X * (row-sum of softmax) = X  (to fp32 ULP)
//
// The layer is algebraically the identity on X. Optimization target is the
// HBM streaming-copy roofline: 2 x 142.6 MB. R1 (cudaMemcpyAsync) hit
// 6.0 TB/s; this round: custom float4 copy, .cs streaming hints (evict-first,
// no L2 retention benefit for a 285 MB one-shot stream), MLP=4 front-batched
// loads per thread.

static constexpr int THREADS = 256;
static constexpr int VEC_PER_THREAD = 4;   // 4 x float4 = 64 B per thread

__global__ __launch_bounds__(THREADS)
void stream_copy_kernel(const float4* __restrict__ in,
                        float4* __restrict__ out,
                        size_t n4) {
    // Block handles a contiguous span of THREADS*VEC_PER_THREAD float4s.
    size_t base = (size_t)blockIdx.x * (THREADS * VEC_PER_THREAD) + threadIdx.x;

    float4 v0, v1, v2, v3;
    // Front-batch all loads (MLP=4), then all stores.
    v0 = __ldcs(in + base + 0 * THREADS);
    v1 = __ldcs(in + base + 1 * THREADS);
    v2 = __ldcs(in + base + 2 * THREADS);
    v3 = __ldcs(in + base + 3 * THREADS);
    __stcs(out + base + 0 * THREADS, v0);
    __stcs(out + base + 1 * THREADS, v1);
    __stcs(out + base + 2 * THREADS, v2);
    __stcs(out + base + 3 * THREADS, v3);
}

// Tail kernel for any remainder (not needed for this shape, but keep the
// launch correct for arbitrary out_size).
__global__ void stream_copy_tail(const float* __restrict__ in,
                                 float* __restrict__ out,
                                 size_t start, size_t n) {
    size_t i = start + blockIdx.x * (size_t)blockDim.x + threadIdx.x;
    if (i < n) out[i] = __ldcs(in + i);
}

extern "C" void kernel_launch(void* const* d_in, const int* in_sizes, int n_in,
                              void* d_out, int out_size) {
    const float* X = (const float*)d_in[0];
    float* out = (float*)d_out;

    size_t n = (size_t)out_size;                 // 35,651,584 floats
    size_t n4 = n / 4;                           // 8,912,896 float4
    size_t per_block = (size_t)THREADS * VEC_PER_THREAD;  // 1024 float4/block
    size_t full_blocks = n4 / per_block;         // 8704 exact for this shape

    if (full_blocks > 0) {
        stream_copy_kernel<<<(unsigned)full_blocks, THREADS>>>(
            (const float4*)X, (float4*)out, n4);
    }
    size_t done = full_blocks * per_block * 4;   // floats covered
    if (done < n) {
        size_t rem = n - done;
        unsigned tb = (unsigned)((rem + 255) / 256);
        stream_copy_tail<<<tb, 256>>>(X, out, done, n);
    }
}